// round 1
// baseline (speedup 1.0000x reference)
#include <cuda_runtime.h>
#include <cuda_bf16.h>

#define KMIX 10

__global__ void __launch_bounds__(256) melnet_gmm_sample_kernel(
    const float* __restrict__ mu,
    const float* __restrict__ log_std,
    const float* __restrict__ pi_logits,
    const float* __restrict__ u_cat,
    const float* __restrict__ eps,
    float* __restrict__ out,
    int n)
{
    int p = blockIdx.x * blockDim.x + threadIdx.x;
    if (p >= n) return;

    // pi_logits row: 10 contiguous floats at float-index p*10 (byte offset 40p, 8B-aligned).
    const float2* pl = reinterpret_cast<const float2*>(pi_logits) + p * 5;
    float2 v0 = __ldg(pl + 0);
    float2 v1 = __ldg(pl + 1);
    float2 v2 = __ldg(pl + 2);
    float2 v3 = __ldg(pl + 3);
    float2 v4 = __ldg(pl + 4);

    float l[KMIX];
    l[0] = v0.x; l[1] = v0.y;
    l[2] = v1.x; l[3] = v1.y;
    l[4] = v2.x; l[5] = v2.y;
    l[6] = v3.x; l[7] = v3.y;
    l[8] = v4.x; l[9] = v4.y;

    // softmax, mimicking jax.nn.softmax fp32 arithmetic:
    //   m = max(l);  e_j = expf(l_j - m);  S = sum(e);  pi_j = e_j / S  (IEEE div)
    float m = l[0];
#pragma unroll
    for (int j = 1; j < KMIX; j++) m = fmaxf(m, l[j]);

    float e[KMIX];
    float S = 0.0f;
#pragma unroll
    for (int j = 0; j < KMIX; j++) {
        e[j] = expf(__fadd_rn(l[j], -m));
        S = __fadd_rn(S, e[j]);
    }

    float u = __ldg(u_cat + p);

    // sequential fp32 cumsum of normalized weights; count strictly-below entries
    float cdf = 0.0f;
    int k = 0;
#pragma unroll
    for (int j = 0; j < KMIX; j++) {
        float pj = __fdiv_rn(e[j], S);   // exact IEEE division, matching reference
        cdf = __fadd_rn(cdf, pj);
        k += (cdf < u) ? 1 : 0;
    }
    if (k > KMIX - 1) k = KMIX - 1;

    // gather only the selected component (saves ~2/3 of mu/log_std traffic)
    int idx = p * KMIX + k;
    float mu_k = __ldg(mu + idx);
    float ls_k = __ldg(log_std + idx);
    float ep   = __ldg(eps + p);

    // out = mu_k + exp(ls_k) * eps   (explicit mul-then-add, no FMA contraction)
    out[p] = __fadd_rn(mu_k, __fmul_rn(expf(ls_k), ep));
}

extern "C" void kernel_launch(void* const* d_in, const int* in_sizes, int n_in,
                              void* d_out, int out_size)
{
    // metadata order: mu, log_std, pi_logits, u_cat, eps
    const float* mu        = (const float*)d_in[0];
    const float* log_std   = (const float*)d_in[1];
    const float* pi_logits = (const float*)d_in[2];
    const float* u_cat     = (const float*)d_in[3];
    const float* eps       = (const float*)d_in[4];
    float* out = (float*)d_out;

    int n = in_sizes[3];   // B*F*T pixels (u_cat element count)

    int threads = 256;
    int blocks = (n + threads - 1) / threads;
    melnet_gmm_sample_kernel<<<blocks, threads>>>(mu, log_std, pi_logits,
                                                  u_cat, eps, out, n);
}

// round 2
// speedup vs baseline: 1.0246x; 1.0246x over previous
#include <cuda_runtime.h>
#include <cuda_bf16.h>

#define KMIX 10

__device__ __forceinline__ float sample_one(const float l[KMIX],
                                            float u,
                                            const float* __restrict__ mu,
                                            const float* __restrict__ log_std,
                                            float ep, int p)
{
    // softmax, mimicking jax.nn.softmax fp32 arithmetic exactly
    float m = l[0];
#pragma unroll
    for (int j = 1; j < KMIX; j++) m = fmaxf(m, l[j]);

    float e[KMIX];
    float S = 0.0f;
#pragma unroll
    for (int j = 0; j < KMIX; j++) {
        e[j] = expf(__fadd_rn(l[j], -m));
        S = __fadd_rn(S, e[j]);
    }

    float cdf = 0.0f;
    int k = 0;
#pragma unroll
    for (int j = 0; j < KMIX; j++) {
        float pj = __fdiv_rn(e[j], S);       // exact IEEE division, matching reference
        cdf = __fadd_rn(cdf, pj);
        k += (cdf < u) ? 1 : 0;
    }
    if (k > KMIX - 1) k = KMIX - 1;

    int idx = p * KMIX + k;
    // streaming loads: no reuse, avoid L2 promotion / L1 pollution on random gathers
    float mu_k = __ldcs(mu + idx);
    float ls_k = __ldcs(log_std + idx);

    return __fadd_rn(mu_k, __fmul_rn(expf(ls_k), ep));
}

__global__ void __launch_bounds__(256) melnet_gmm_sample_kernel2(
    const float* __restrict__ mu,
    const float* __restrict__ log_std,
    const float* __restrict__ pi_logits,
    const float* __restrict__ u_cat,
    const float* __restrict__ eps,
    float* __restrict__ out,
    int n)   // n = number of PIXEL PAIRS
{
    int t = blockIdx.x * blockDim.x + threadIdx.x;
    if (t >= n) return;

    int p0 = 2 * t;
    int p1 = 2 * t + 1;

    // two adjacent rows = 80 B, 16B-aligned at byte offset 80*t -> five LDG.128
    const float4* pl = reinterpret_cast<const float4*>(pi_logits) + t * 5;
    float4 q0 = __ldcs(pl + 0);
    float4 q1 = __ldcs(pl + 1);
    float4 q2 = __ldcs(pl + 2);
    float4 q3 = __ldcs(pl + 3);
    float4 q4 = __ldcs(pl + 4);

    float2 u2 = __ldcs(reinterpret_cast<const float2*>(u_cat) + t);
    float2 e2 = __ldcs(reinterpret_cast<const float2*>(eps) + t);

    float lA[KMIX] = { q0.x, q0.y, q0.z, q0.w,
                       q1.x, q1.y, q1.z, q1.w,
                       q2.x, q2.y };
    float lB[KMIX] = { q2.z, q2.w,
                       q3.x, q3.y, q3.z, q3.w,
                       q4.x, q4.y, q4.z, q4.w };

    float oA = sample_one(lA, u2.x, mu, log_std, e2.x, p0);
    float oB = sample_one(lB, u2.y, mu, log_std, e2.y, p1);

    reinterpret_cast<float2*>(out)[t] = make_float2(oA, oB);
}

extern "C" void kernel_launch(void* const* d_in, const int* in_sizes, int n_in,
                              void* d_out, int out_size)
{
    // metadata order: mu, log_std, pi_logits, u_cat, eps
    const float* mu        = (const float*)d_in[0];
    const float* log_std   = (const float*)d_in[1];
    const float* pi_logits = (const float*)d_in[2];
    const float* u_cat     = (const float*)d_in[3];
    const float* eps       = (const float*)d_in[4];
    float* out = (float*)d_out;

    int n = in_sizes[3];       // B*F*T pixels (4,194,304 — even)
    int npairs = n / 2;

    int threads = 256;
    int blocks = (npairs + threads - 1) / threads;
    melnet_gmm_sample_kernel2<<<blocks, threads>>>(mu, log_std, pi_logits,
                                                   u_cat, eps, out, npairs);
}